// round 15
// baseline (speedup 1.0000x reference)
#include <cuda_runtime.h>
#include <cuda_fp16.h>
#include <math.h>
#include <mma.h>

using namespace nvcuda;

// ---------------- model constants ----------------
constexpr int Dm  = 768;
constexpr int DIm = 1536;
constexpr int Nst = 16;
constexpr int NLs = 8;
constexpr int Bb  = 2;
constexpr int Ll  = 1024;
constexpr int Mrows = Bb * Ll;          // 2048
constexpr float EPSf = 1e-5f;
constexpr int CH = 32;                  // scan chunks
constexpr int CL = Ll / CH;             // 32 steps per chunk
constexpr int DBL_LD = 128;             // padded dbl row stride
constexpr int SPK = 8;                  // split-K factor for x_proj

// ---------------- fp32 scratch ----------------
constexpr size_t OFF_RES = 0;
constexpr size_t OFF_X   = OFF_RES + (size_t)Mrows * Dm;
constexpr size_t OFF_XZ  = OFF_X   + (size_t)Mrows * Dm;
constexpr size_t OFF_XC  = OFF_XZ  + (size_t)Mrows * 2 * DIm;
constexpr size_t OFF_DT  = OFF_XC  + (size_t)Mrows * DIm;       // dt_lin
constexpr size_t OFF_DBL = OFF_DT  + (size_t)Mrows * DIm;       // Mrows x 128
constexpr size_t CHSZ    = (size_t)Bb * CH * DIm * Nst;
constexpr size_t OFF_CHE = OFF_DBL + (size_t)Mrows * DBL_LD;
constexpr size_t OFF_APR = OFF_CHE + CHSZ;
constexpr size_t OFF_PRE = OFF_APR + CHSZ;
constexpr size_t OFF_SPL = OFF_PRE + CHSZ;                      // split-K partials
constexpr size_t SCRATCH_TOTAL = OFF_SPL + (size_t)Mrows * DBL_LD * SPK;

__device__ float g_scratch[SCRATCH_TOTAL];

// ---------------- fp16 weight scratch ----------------
constexpr size_t HSZ_IN  = (size_t)NLs * 2 * DIm * Dm;
constexpr size_t HSZ_OUT = (size_t)NLs * Dm * DIm;
constexpr size_t HSZ_XW  = (size_t)NLs * 128 * DIm;
constexpr size_t HSZ_DW  = (size_t)NLs * DIm * 64;
constexpr size_t HOFF_IN  = 0;
constexpr size_t HOFF_OUT = HOFF_IN  + HSZ_IN;
constexpr size_t HOFF_XW  = HOFF_OUT + HSZ_OUT;
constexpr size_t HOFF_DW  = HOFF_XW  + HSZ_XW;
constexpr size_t HTOTAL   = HOFF_DW  + HSZ_DW;

__device__ __half g_wh[HTOTAL];

// ---------------- fp16 activation scratch ----------------
constexpr size_t AOFF_H16   = 0;
constexpr size_t AOFF_XC16  = AOFF_H16  + (size_t)Mrows * Dm;
constexpr size_t AOFF_DBL16 = AOFF_XC16 + (size_t)Mrows * DIm;
constexpr size_t AOFF_Y16   = AOFF_DBL16 + (size_t)Mrows * DBL_LD;
constexpr size_t ATOTAL     = AOFF_Y16  + (size_t)Mrows * DIm;

__device__ __half g_act[ATOTAL];

// ---------------- cp.async helpers ----------------
__device__ __forceinline__ void cp16(void* smem_ptr, const void* gmem_ptr)
{
    unsigned s = (unsigned)__cvta_generic_to_shared(smem_ptr);
    asm volatile("cp.async.cg.shared.global [%0], [%1], 16;\n" :: "r"(s), "l"(gmem_ptr));
}
__device__ __forceinline__ void cp_commit()
{
    asm volatile("cp.async.commit_group;\n" ::: "memory");
}
template <int N>
__device__ __forceinline__ void cp_wait()
{
    asm volatile("cp.async.wait_group %0;\n" :: "n"(N) : "memory");
}

// ---------------- vectorized fp32 -> fp16 pack ----------------
__device__ __forceinline__ uint4 pack8(const float4& a, const float4& b)
{
    __half2 h0 = __floats2half2_rn(a.x, a.y);
    __half2 h1 = __floats2half2_rn(a.z, a.w);
    __half2 h2 = __floats2half2_rn(b.x, b.y);
    __half2 h3 = __floats2half2_rn(b.z, b.w);
    uint4 o;
    o.x = *(const unsigned*)&h0;
    o.y = *(const unsigned*)&h1;
    o.z = *(const unsigned*)&h2;
    o.w = *(const unsigned*)&h3;
    return o;
}

// ---------------- merged weight conversion / padding ----------------
constexpr size_t V_IN  = HSZ_IN  / 8;
constexpr size_t V_OUT = HSZ_OUT / 8;
constexpr size_t V_XW  = (size_t)NLs * 128 * (DIm / 8);
constexpr size_t V_DW  = (size_t)NLs * DIm * (64 / 8);
constexpr size_t V_TOTAL = V_IN + V_OUT + V_XW + V_DW;

__global__ void convert_weights_kernel(const float* __restrict__ in_w,
                                       const float* __restrict__ out_w,
                                       const float* __restrict__ xw,
                                       const float* __restrict__ dw,
                                       uint4* __restrict__ wh)
{
    size_t v = (size_t)blockIdx.x * blockDim.x + threadIdx.x;
    if (v >= V_TOTAL) return;
    if (v < V_IN) {
        const float4* s = (const float4*)in_w + 2 * v;
        wh[HOFF_IN / 8 + v] = pack8(s[0], s[1]);
    } else if (v < V_IN + V_OUT) {
        size_t u = v - V_IN;
        const float4* s = (const float4*)out_w + 2 * u;
        wh[HOFF_OUT / 8 + u] = pack8(s[0], s[1]);
    } else if (v < V_IN + V_OUT + V_XW) {
        size_t u = v - V_IN - V_OUT;
        constexpr int KV = DIm / 8;
        int l = (int)(u / (128 * KV));
        int rem = (int)(u - (size_t)l * (128 * KV));
        int r = rem / KV;
        int kv = rem - r * KV;
        if (r < 80) {
            const float4* s = (const float4*)(xw + ((size_t)l * 80 + r) * DIm) + 2 * kv;
            wh[HOFF_XW / 8 + u] = pack8(s[0], s[1]);
        } else {
            wh[HOFF_XW / 8 + u] = make_uint4(0, 0, 0, 0);
        }
    } else {
        size_t u = v - V_IN - V_OUT - V_XW;
        int ld = (int)(u >> 3);
        int cv = (int)(u & 7);
        if (cv < 6) {
            const float4* s = (const float4*)(dw + (size_t)ld * 48) + 2 * cv;
            wh[HOFF_DW / 8 + u] = pack8(s[0], s[1]);
        } else {
            wh[HOFF_DW / 8 + u] = make_uint4(0, 0, 0, 0);
        }
    }
}

// ---------------- split-K reduce + fp16 convert (dbl, dbl16) ----------------
__global__ void reduce_spl_kernel(const float4* __restrict__ spl,
                                  float4* __restrict__ dbl,
                                  uint2* __restrict__ dbl16v,
                                  int n4)
{
    int i = blockIdx.x * blockDim.x + threadIdx.x;
    if (i >= n4) return;
    float4 acc = spl[i];
#pragma unroll
    for (int s = 1; s < SPK; s++) {
        float4 v = spl[(size_t)s * n4 + i];
        acc.x += v.x; acc.y += v.y; acc.z += v.z; acc.w += v.w;
    }
    dbl[i] = acc;
    __half2 h0 = __floats2half2_rn(acc.x, acc.y);
    __half2 h1 = __floats2half2_rn(acc.z, acc.w);
    uint2 o;
    o.x = *(const unsigned*)&h0;
    o.y = *(const unsigned*)&h1;
    dbl16v[i] = o;
}

// ---------------- embedding gather ----------------
__global__ void embed_kernel(const int* __restrict__ ids,
                             const float* __restrict__ emb,
                             float* __restrict__ res)
{
    int idx = blockIdx.x * blockDim.x + threadIdx.x;
    if (idx >= Mrows * Dm) return;
    int row = idx / Dm;
    int c   = idx - row * Dm;
    res[idx] = emb[(size_t)ids[row] * Dm + c];
}

// ---------------- residual add + RMSNorm (fp16 and/or fp32 out) ----------------
__global__ void rms_resid_kernel(float* __restrict__ res,
                                 const float* __restrict__ xadd,
                                 const float* __restrict__ w,
                                 float* __restrict__ out32,
                                 __half* __restrict__ out16,
                                 int addx)
{
    const int row = blockIdx.x;
    const int tid = threadIdx.x;
    float v[3];
    float local = 0.f;
#pragma unroll
    for (int j = 0; j < 3; j++) {
        int c = tid + j * 256;
        float t = res[(size_t)row * Dm + c];
        if (addx) {
            t += xadd[(size_t)row * Dm + c];
            res[(size_t)row * Dm + c] = t;
        }
        v[j] = t;
        local += t * t;
    }
#pragma unroll
    for (int o = 16; o > 0; o >>= 1) local += __shfl_xor_sync(0xffffffffu, local, o);
    __shared__ float warpsum[8];
    __shared__ float sscale;
    if ((tid & 31) == 0) warpsum[tid >> 5] = local;
    __syncthreads();
    if (tid == 0) {
        float t = 0.f;
#pragma unroll
        for (int j = 0; j < 8; j++) t += warpsum[j];
        sscale = rsqrtf(t / (float)Dm + EPSf);
    }
    __syncthreads();
    float sc = sscale;
#pragma unroll
    for (int j = 0; j < 3; j++) {
        int c = tid + j * 256;
        float o = v[j] * sc * w[c];
        if (out32) out32[(size_t)row * Dm + c] = o;
        if (out16) out16[(size_t)row * Dm + c] = __float2half_rn(o);
    }
}

// ============================================================================
// Pure-FP16 tensor-core GEMM, fp32 accumulate, 2-stage cp.async, BK=64.
// 128 threads = 4 warps (2m x 2n); warp tile 64 x (BN/2).
// C[M,N] = A[M,K](fp16, lda) @ W[N,K]^T(fp16, row stride wstride).
// Optional split-K via gridDim.z (K = split length, C offset cspl per z).
// BM=128, BN in {128,64}, BK=64.  Dynamic smem: 2*(BM+BN)*72 halves.
// Requires K % 64 == 0.
// ============================================================================
template <int BN>
__global__ __launch_bounds__(128)
void hgemm16_tn(const __half* __restrict__ A, int lda,
                const __half* __restrict__ W, int wstride,
                float* __restrict__ C, int ldc, int K,
                size_t cspl)
{
    constexpr int BM = 128;
    constexpr int BK = 64;
    constexpr int LD = BK + 8;       // 72 halves = 144B rows (16B aligned)
    constexpr int WM = 64;
    constexpr int WN = BN / 2;       // 64 or 32
    constexpr int AF = WM / 16;      // 4
    constexpr int BF = WN / 16;      // 4 or 2

    extern __shared__ __half sh[];
    __half* AsB = sh;                        // 2 * BM * LD
    __half* WsB = sh + 2 * BM * LD;          // 2 * BN * LD

    const int z = blockIdx.z;
    A += (size_t)z * K;
    W += (size_t)z * K;
    C += (size_t)z * cspl;

    const int t    = threadIdx.x;
    const int warp = t >> 5;
    const int wm   = (warp & 1) * WM;
    const int wn   = (warp >> 1) * WN;
    const int bm   = blockIdx.y * BM;
    const int bn   = blockIdx.x * BN;

    auto issue = [&](int stage, int k0) {
        __half* Ab = AsB + (size_t)stage * BM * LD;
        __half* Wb = WsB + (size_t)stage * BN * LD;
#pragma unroll
        for (int i = 0; i < 8; i++) {            // A: 128 rows x 64 halves
            int u = t + i * 128;
            int r = u >> 3, c = (u & 7) * 8;
            cp16(&Ab[(size_t)r * LD + c], A + (size_t)(bm + r) * lda + k0 + c);
        }
#pragma unroll
        for (int i = 0; i < BN / 16; i++) {      // W: BN rows x 64 halves
            int u = t + i * 128;
            int r = u >> 3, c = (u & 7) * 8;
            cp16(&Wb[(size_t)r * LD + c], W + (size_t)(bn + r) * wstride + k0 + c);
        }
        cp_commit();
    };

    wmma::fragment<wmma::accumulator, 16, 16, 16, float> acc[AF][BF];
#pragma unroll
    for (int i = 0; i < AF; i++)
#pragma unroll
        for (int j = 0; j < BF; j++)
            wmma::fill_fragment(acc[i][j], 0.f);

    const int nt = K / BK;

    issue(0, 0);
    cp_wait<0>();
    __syncthreads();

    for (int tt = 0; tt < nt; ++tt) {
        const int buf = tt & 1;
        const bool more = (tt + 1 < nt);
        if (more) issue(buf ^ 1, (tt + 1) * BK);

        const __half* Abuf = AsB + (size_t)buf * BM * LD;
        const __half* Wbuf = WsB + (size_t)buf * BN * LD;
#pragma unroll
        for (int kk = 0; kk < BK; kk += 16) {
            wmma::fragment<wmma::matrix_a, 16, 16, 16, __half, wmma::row_major> af[AF];
            wmma::fragment<wmma::matrix_b, 16, 16, 16, __half, wmma::col_major> bf[BF];
#pragma unroll
            for (int i = 0; i < AF; i++)
                wmma::load_matrix_sync(af[i], Abuf + (size_t)(wm + i * 16) * LD + kk, LD);
#pragma unroll
            for (int j = 0; j < BF; j++)
                wmma::load_matrix_sync(bf[j], Wbuf + (size_t)(wn + j * 16) * LD + kk, LD);
#pragma unroll
            for (int i = 0; i < AF; i++)
#pragma unroll
                for (int j = 0; j < BF; j++)
                    wmma::mma_sync(acc[i][j], af[i], bf[j], acc[i][j]);
        }

        if (more) cp_wait<0>();
        __syncthreads();
    }

#pragma unroll
    for (int i = 0; i < AF; i++)
#pragma unroll
        for (int j = 0; j < BF; j++)
            wmma::store_matrix_sync(&C[(size_t)(bm + wm + i * 16) * ldc + bn + wn + j * 16],
                                    acc[i][j], ldc, wmma::mem_row_major);
}

constexpr int SMEM_G128 = 2 * (128 + 128) * 72 * 2;   // 73728
constexpr int SMEM_G64  = 2 * (128 + 64)  * 72 * 2;   // 55296

// ---------------- depthwise causal conv (K=4) + SiLU, fp32+fp16 out ----------------
__global__ void conv_silu_kernel(const float* __restrict__ xz,
                                 const float* __restrict__ w,
                                 const float* __restrict__ bias,
                                 float* __restrict__ xc,
                                 __half* __restrict__ xc16)
{
    int idx = blockIdx.x * blockDim.x + threadIdx.x;
    if (idx >= Mrows * DIm) return;
    int row = idx / DIm;
    int c   = idx - row * DIm;
    int l   = row & (Ll - 1);
    float s = bias[c];
#pragma unroll
    for (int k = 0; k < 4; k++) {
        int ll = l - 3 + k;
        if (ll >= 0) s += w[c * 4 + k] * xz[(size_t)(row - 3 + k) * (2 * DIm) + c];
    }
    float o = s / (1.f + expf(-s));
    xc[idx] = o;
    xc16[idx] = __float2half_rn(o);
}

// ============================================================================
// Chunked selective scan: 1 thread per (b, chunk, channel), 16 states in regs.
// ============================================================================
__device__ __forceinline__ float softplus_f(float x)
{
    return (x > 20.f) ? x : log1pf(__expf(x));
}

__global__ void scan_pass1(const float* __restrict__ xc,
                           const float* __restrict__ dtl,
                           const float* __restrict__ dbl,
                           const float* __restrict__ A_log,
                           const float* __restrict__ dtb_bias,
                           float* __restrict__ chk_end,
                           float* __restrict__ aprod)
{
    int d = blockIdx.x * blockDim.x + threadIdx.x;
    int c = blockIdx.y;
    int b = blockIdx.z;
    if (d >= DIm) return;

    float Ac[16], st[16];
#pragma unroll
    for (int n = 0; n < 16; n++) {
        Ac[n] = -expf(A_log[(size_t)d * 16 + n]);
        st[n] = 0.f;
    }
    const float db = dtb_bias[d];
    float sumdt = 0.f;

    const int l0 = c * CL;
    const float* xcb = xc  + ((size_t)b * Ll + l0) * DIm + d;
    const float* dtb = dtl + ((size_t)b * Ll + l0) * DIm + d;
    const float* blb = dbl + ((size_t)b * Ll + l0) * DBL_LD;

    for (int l = 0; l < CL; l++) {
        float u   = xcb[(size_t)l * DIm];
        float dtt = softplus_f(dtb[(size_t)l * DIm] + db);
        float du  = dtt * u;
        sumdt += dtt;
        const float4* B4 = (const float4*)(blb + (size_t)l * DBL_LD + 48);
#pragma unroll
        for (int j = 0; j < 4; j++) {
            float4 Bv = B4[j];
            st[4*j+0] = fmaf(__expf(dtt * Ac[4*j+0]), st[4*j+0], du * Bv.x);
            st[4*j+1] = fmaf(__expf(dtt * Ac[4*j+1]), st[4*j+1], du * Bv.y);
            st[4*j+2] = fmaf(__expf(dtt * Ac[4*j+2]), st[4*j+2], du * Bv.z);
            st[4*j+3] = fmaf(__expf(dtt * Ac[4*j+3]), st[4*j+3], du * Bv.w);
        }
    }
    size_t base = (((size_t)b * CH + c) * DIm + d) * 16;
#pragma unroll
    for (int n = 0; n < 16; n++) {
        chk_end[base + n] = st[n];
        aprod[base + n]   = __expf(sumdt * Ac[n]);
    }
}

__global__ void scan_pass2(const float* __restrict__ chk_end,
                           const float* __restrict__ aprod,
                           float* __restrict__ chk_pref)
{
    int idx = blockIdx.x * blockDim.x + threadIdx.x;
    if (idx >= Bb * DIm * Nst) return;
    int b = idx / (DIm * Nst);
    int r = idx - b * (DIm * Nst);
    float hv = 0.f;
#pragma unroll
    for (int c = 0; c < CH; c++) {
        size_t o = ((size_t)b * CH + c) * DIm * Nst + r;
        chk_pref[o] = hv;
        hv = fmaf(aprod[o], hv, chk_end[o]);
    }
}

__global__ void scan_pass3(const float* __restrict__ xc,
                           const float* __restrict__ dtl,
                           const float* __restrict__ dbl,
                           const float* __restrict__ A_log,
                           const float* __restrict__ dtb_bias,
                           const float* __restrict__ Dp,
                           const float* __restrict__ xz,
                           const float* __restrict__ chk_pref,
                           __half* __restrict__ y16)
{
    int d = blockIdx.x * blockDim.x + threadIdx.x;
    int c = blockIdx.y;
    int b = blockIdx.z;
    if (d >= DIm) return;

    float Ac[16], st[16];
#pragma unroll
    for (int n = 0; n < 16; n++)
        Ac[n] = -expf(A_log[(size_t)d * 16 + n]);
    {
        size_t base = (((size_t)b * CH + c) * DIm + d) * 16;
#pragma unroll
        for (int n = 0; n < 16; n++) st[n] = chk_pref[base + n];
    }
    const float db = dtb_bias[d];
    const float dp = Dp[d];

    const int l0 = c * CL;
    const float* xcb = xc  + ((size_t)b * Ll + l0) * DIm + d;
    const float* dtb = dtl + ((size_t)b * Ll + l0) * DIm + d;
    const float* zb  = xz  + ((size_t)b * Ll + l0) * (2 * DIm) + DIm + d;
    const float* blb = dbl + ((size_t)b * Ll + l0) * DBL_LD;
    __half*      yb  = y16 + ((size_t)b * Ll + l0) * DIm + d;

    for (int l = 0; l < CL; l++) {
        float u   = xcb[(size_t)l * DIm];
        float dtt = softplus_f(dtb[(size_t)l * DIm] + db);
        float du  = dtt * u;
        const float4* B4 = (const float4*)(blb + (size_t)l * DBL_LD + 48);
        const float4* C4 = (const float4*)(blb + (size_t)l * DBL_LD + 64);
        float yv = 0.f;
#pragma unroll
        for (int j = 0; j < 4; j++) {
            float4 Bv = B4[j];
            float4 Cv = C4[j];
            st[4*j+0] = fmaf(__expf(dtt * Ac[4*j+0]), st[4*j+0], du * Bv.x);
            st[4*j+1] = fmaf(__expf(dtt * Ac[4*j+1]), st[4*j+1], du * Bv.y);
            st[4*j+2] = fmaf(__expf(dtt * Ac[4*j+2]), st[4*j+2], du * Bv.z);
            st[4*j+3] = fmaf(__expf(dtt * Ac[4*j+3]), st[4*j+3], du * Bv.w);
            yv = fmaf(st[4*j+0], Cv.x, yv);
            yv = fmaf(st[4*j+1], Cv.y, yv);
            yv = fmaf(st[4*j+2], Cv.z, yv);
            yv = fmaf(st[4*j+3], Cv.w, yv);
        }
        float z = zb[(size_t)l * (2 * DIm)];
        yv = fmaf(u, dp, yv);
        yb[(size_t)l * DIm] = __float2half_rn(yv * (z / (1.f + __expf(-z))));
    }
}

// ---------------- host launcher ----------------
extern "C" void kernel_launch(void* const* d_in, const int* in_sizes, int n_in,
                              void* d_out, int out_size)
{
    const int*   ids       = (const int*)  d_in[0];
    const float* emb       = (const float*)d_in[1];
    const float* in_proj_w = (const float*)d_in[2];
    const float* conv_w    = (const float*)d_in[3];
    const float* conv_b    = (const float*)d_in[4];
    const float* x_proj_w  = (const float*)d_in[5];
    const float* dt_proj_w = (const float*)d_in[6];
    const float* dt_proj_b = (const float*)d_in[7];
    const float* A_log     = (const float*)d_in[8];
    const float* D_param   = (const float*)d_in[9];
    const float* out_proj_w= (const float*)d_in[10];
    const float* norm_w    = (const float*)d_in[11];
    const float* norm_f_w  = (const float*)d_in[12];
    float* out = (float*)d_out;

    float* s = nullptr;
    cudaGetSymbolAddress((void**)&s, g_scratch);
    __half* wh = nullptr;
    cudaGetSymbolAddress((void**)&wh, g_wh);
    __half* ah = nullptr;
    cudaGetSymbolAddress((void**)&ah, g_act);

    float* res = s + OFF_RES;
    float* x   = s + OFF_X;
    float* xz  = s + OFF_XZ;
    float* xc  = s + OFF_XC;
    float* dtl = s + OFF_DT;
    float* dbl = s + OFF_DBL;
    float* che = s + OFF_CHE;
    float* apr = s + OFF_APR;
    float* pre = s + OFF_PRE;
    float* spl = s + OFF_SPL;

    __half* w_in   = wh + HOFF_IN;
    __half* w_out  = wh + HOFF_OUT;
    __half* w_xw   = wh + HOFF_XW;
    __half* w_dw   = wh + HOFF_DW;
    __half* h16    = ah + AOFF_H16;
    __half* xc16   = ah + AOFF_XC16;
    __half* dbl16  = ah + AOFF_DBL16;
    __half* y16    = ah + AOFF_Y16;

    cudaFuncSetAttribute(hgemm16_tn<128>, cudaFuncAttributeMaxDynamicSharedMemorySize, SMEM_G128);
    cudaFuncSetAttribute(hgemm16_tn<64>,  cudaFuncAttributeMaxDynamicSharedMemorySize, SMEM_G64);

    // 1) merged weight conversion / padding
    convert_weights_kernel<<<(int)((V_TOTAL + 255) / 256), 256>>>(
        in_proj_w, out_proj_w, x_proj_w, dt_proj_w, (uint4*)wh);

    // 2) embedding
    embed_kernel<<<(Mrows * Dm + 255) / 256, 256>>>(ids, emb, res);

    for (int i = 0; i < NLs; i++) {
        // 3) h16 = fp16(rms(res += x))
        rms_resid_kernel<<<Mrows, 256>>>(res, x, norm_w + (size_t)i * Dm,
                                         nullptr, h16, i > 0);

        // 4) xz = h16 @ in_proj^T   [2048, 3072], K=768   <- profiled launch
        {
            dim3 g(2 * DIm / 128, Mrows / 128, 1);
            hgemm16_tn<128><<<g, 128, SMEM_G128>>>(h16, Dm,
                w_in + (size_t)i * 2 * DIm * Dm, Dm, xz, 2 * DIm, Dm, 0);
        }

        // xc/xc16 = silu(causal depthwise conv(xi) + b)
        conv_silu_kernel<<<(Mrows * DIm + 255) / 256, 256>>>(
            xz, conv_w + (size_t)i * DIm * 4, conv_b + (size_t)i * DIm, xc, xc16);

        // dbl partials = xc16 @ xw_pad^T (split-K x SPK)  [2048, 128], K=1536
        {
            dim3 g(128 / 64, Mrows / 128, SPK);
            hgemm16_tn<64><<<g, 128, SMEM_G64>>>(xc16, DIm,
                w_xw + (size_t)i * 128 * DIm, DIm,
                spl, DBL_LD, DIm / SPK, (size_t)Mrows * DBL_LD);
        }

        // reduce partials -> dbl (fp32) + dbl16 (fp16)
        {
            int n4 = Mrows * DBL_LD / 4;
            reduce_spl_kernel<<<(n4 + 255) / 256, 256>>>(
                (const float4*)spl, (float4*)dbl, (uint2*)dbl16, n4);
        }

        // dt_lin = dbl16[:, :64] @ dw_pad^T   [2048, 1536], K=64
        {
            dim3 g(DIm / 128, Mrows / 128, 1);
            hgemm16_tn<128><<<g, 128, SMEM_G128>>>(dbl16, DBL_LD,
                w_dw + (size_t)i * DIm * 64, 64, dtl, DIm, 64, 0);
        }

        // chunked selective scan (1 thread / channel)
        {
            dim3 g1(DIm / 256, CH, Bb);
            scan_pass1<<<g1, 256>>>(xc, dtl, dbl, A_log + (size_t)i * DIm * Nst,
                                    dt_proj_b + (size_t)i * DIm, che, apr);
            scan_pass2<<<(Bb * DIm * Nst + 255) / 256, 256>>>(che, apr, pre);
            scan_pass3<<<g1, 256>>>(xc, dtl, dbl, A_log + (size_t)i * DIm * Nst,
                                    dt_proj_b + (size_t)i * DIm,
                                    D_param + (size_t)i * DIm, xz, pre, y16);
        }

        // x = y16 @ out_proj^T   [2048, 768], K=1536
        {
            dim3 g(Dm / 64, Mrows / 128, 1);
            hgemm16_tn<64><<<g, 128, SMEM_G64>>>(y16, DIm,
                w_out + (size_t)i * Dm * DIm, DIm, x, Dm, DIm, 0);
        }
    }

    // final: out = rms(res + x) * norm_f_w   (fp32)
    rms_resid_kernel<<<Mrows, 256>>>(res, x, norm_f_w, out, nullptr, 1);
}

// round 16
// speedup vs baseline: 1.4693x; 1.4693x over previous
#include <cuda_runtime.h>
#include <cuda_fp16.h>
#include <math.h>
#include <mma.h>

using namespace nvcuda;

// ---------------- model constants ----------------
constexpr int Dm  = 768;
constexpr int DIm = 1536;
constexpr int Nst = 16;
constexpr int NLs = 8;
constexpr int Bb  = 2;
constexpr int Ll  = 1024;
constexpr int Mrows = Bb * Ll;          // 2048
constexpr float EPSf = 1e-5f;
constexpr int CH = 32;                  // scan chunks
constexpr int CL = Ll / CH;             // 32 steps per chunk
constexpr int DBL_LD = 128;             // padded dbl row stride
constexpr int SPK = 8;                  // split-K factor for x_proj

// ---------------- fp32 scratch ----------------
constexpr size_t OFF_RES = 0;
constexpr size_t OFF_X   = OFF_RES + (size_t)Mrows * Dm;
constexpr size_t OFF_XZ  = OFF_X   + (size_t)Mrows * Dm;
constexpr size_t OFF_XC  = OFF_XZ  + (size_t)Mrows * 2 * DIm;
constexpr size_t OFF_DT  = OFF_XC  + (size_t)Mrows * DIm;       // dt_lin
constexpr size_t OFF_DBL = OFF_DT  + (size_t)Mrows * DIm;       // Mrows x 128
constexpr size_t CHSZ    = (size_t)Bb * CH * DIm * Nst;
constexpr size_t OFF_CHE = OFF_DBL + (size_t)Mrows * DBL_LD;
constexpr size_t OFF_APR = OFF_CHE + CHSZ;
constexpr size_t OFF_PRE = OFF_APR + CHSZ;
constexpr size_t OFF_SPL = OFF_PRE + CHSZ;                      // split-K partials
constexpr size_t SCRATCH_TOTAL = OFF_SPL + (size_t)Mrows * DBL_LD * SPK;

__device__ float g_scratch[SCRATCH_TOTAL];

// ---------------- fp16 weight scratch ----------------
constexpr size_t HSZ_IN  = (size_t)NLs * 2 * DIm * Dm;
constexpr size_t HSZ_OUT = (size_t)NLs * Dm * DIm;
constexpr size_t HSZ_XW  = (size_t)NLs * 128 * DIm;
constexpr size_t HSZ_DW  = (size_t)NLs * DIm * 64;
constexpr size_t HOFF_IN  = 0;
constexpr size_t HOFF_OUT = HOFF_IN  + HSZ_IN;
constexpr size_t HOFF_XW  = HOFF_OUT + HSZ_OUT;
constexpr size_t HOFF_DW  = HOFF_XW  + HSZ_XW;
constexpr size_t HTOTAL   = HOFF_DW  + HSZ_DW;

__device__ __half g_wh[HTOTAL];

// ---------------- fp16 activation scratch ----------------
constexpr size_t AOFF_H16   = 0;
constexpr size_t AOFF_XC16  = AOFF_H16  + (size_t)Mrows * Dm;
constexpr size_t AOFF_DBL16 = AOFF_XC16 + (size_t)Mrows * DIm;
constexpr size_t AOFF_Y16   = AOFF_DBL16 + (size_t)Mrows * DBL_LD;
constexpr size_t ATOTAL     = AOFF_Y16  + (size_t)Mrows * DIm;

__device__ __half g_act[ATOTAL];

// ---------------- cp.async helpers ----------------
__device__ __forceinline__ void cp16(void* smem_ptr, const void* gmem_ptr)
{
    unsigned s = (unsigned)__cvta_generic_to_shared(smem_ptr);
    asm volatile("cp.async.cg.shared.global [%0], [%1], 16;\n" :: "r"(s), "l"(gmem_ptr));
}
__device__ __forceinline__ void cp_commit()
{
    asm volatile("cp.async.commit_group;\n" ::: "memory");
}
template <int N>
__device__ __forceinline__ void cp_wait()
{
    asm volatile("cp.async.wait_group %0;\n" :: "n"(N) : "memory");
}

// ---------------- vectorized fp32 -> fp16 pack ----------------
__device__ __forceinline__ uint4 pack8(const float4& a, const float4& b)
{
    __half2 h0 = __floats2half2_rn(a.x, a.y);
    __half2 h1 = __floats2half2_rn(a.z, a.w);
    __half2 h2 = __floats2half2_rn(b.x, b.y);
    __half2 h3 = __floats2half2_rn(b.z, b.w);
    uint4 o;
    o.x = *(const unsigned*)&h0;
    o.y = *(const unsigned*)&h1;
    o.z = *(const unsigned*)&h2;
    o.w = *(const unsigned*)&h3;
    return o;
}

// ---------------- merged weight conversion / padding ----------------
constexpr size_t V_IN  = HSZ_IN  / 8;
constexpr size_t V_OUT = HSZ_OUT / 8;
constexpr size_t V_XW  = (size_t)NLs * 128 * (DIm / 8);
constexpr size_t V_DW  = (size_t)NLs * DIm * (64 / 8);
constexpr size_t V_TOTAL = V_IN + V_OUT + V_XW + V_DW;

__global__ void convert_weights_kernel(const float* __restrict__ in_w,
                                       const float* __restrict__ out_w,
                                       const float* __restrict__ xw,
                                       const float* __restrict__ dw,
                                       uint4* __restrict__ wh)
{
    size_t v = (size_t)blockIdx.x * blockDim.x + threadIdx.x;
    if (v >= V_TOTAL) return;
    if (v < V_IN) {
        const float4* s = (const float4*)in_w + 2 * v;
        wh[HOFF_IN / 8 + v] = pack8(s[0], s[1]);
    } else if (v < V_IN + V_OUT) {
        size_t u = v - V_IN;
        const float4* s = (const float4*)out_w + 2 * u;
        wh[HOFF_OUT / 8 + u] = pack8(s[0], s[1]);
    } else if (v < V_IN + V_OUT + V_XW) {
        size_t u = v - V_IN - V_OUT;
        constexpr int KV = DIm / 8;
        int l = (int)(u / (128 * KV));
        int rem = (int)(u - (size_t)l * (128 * KV));
        int r = rem / KV;
        int kv = rem - r * KV;
        if (r < 80) {
            const float4* s = (const float4*)(xw + ((size_t)l * 80 + r) * DIm) + 2 * kv;
            wh[HOFF_XW / 8 + u] = pack8(s[0], s[1]);
        } else {
            wh[HOFF_XW / 8 + u] = make_uint4(0, 0, 0, 0);
        }
    } else {
        size_t u = v - V_IN - V_OUT - V_XW;
        int ld = (int)(u >> 3);
        int cv = (int)(u & 7);
        if (cv < 6) {
            const float4* s = (const float4*)(dw + (size_t)ld * 48) + 2 * cv;
            wh[HOFF_DW / 8 + u] = pack8(s[0], s[1]);
        } else {
            wh[HOFF_DW / 8 + u] = make_uint4(0, 0, 0, 0);
        }
    }
}

// ---------------- split-K reduce + fp16 convert (dbl, dbl16) ----------------
__global__ void reduce_spl_kernel(const float4* __restrict__ spl,
                                  float4* __restrict__ dbl,
                                  uint2* __restrict__ dbl16v,
                                  int n4)
{
    int i = blockIdx.x * blockDim.x + threadIdx.x;
    if (i >= n4) return;
    float4 acc = spl[i];
#pragma unroll
    for (int s = 1; s < SPK; s++) {
        float4 v = spl[(size_t)s * n4 + i];
        acc.x += v.x; acc.y += v.y; acc.z += v.z; acc.w += v.w;
    }
    dbl[i] = acc;
    __half2 h0 = __floats2half2_rn(acc.x, acc.y);
    __half2 h1 = __floats2half2_rn(acc.z, acc.w);
    uint2 o;
    o.x = *(const unsigned*)&h0;
    o.y = *(const unsigned*)&h1;
    dbl16v[i] = o;
}

// ---------------- embedding gather ----------------
__global__ void embed_kernel(const int* __restrict__ ids,
                             const float* __restrict__ emb,
                             float* __restrict__ res)
{
    int idx = blockIdx.x * blockDim.x + threadIdx.x;
    if (idx >= Mrows * Dm) return;
    int row = idx / Dm;
    int c   = idx - row * Dm;
    res[idx] = emb[(size_t)ids[row] * Dm + c];
}

// ---------------- residual add + RMSNorm (fp16 and/or fp32 out) ----------------
__global__ void rms_resid_kernel(float* __restrict__ res,
                                 const float* __restrict__ xadd,
                                 const float* __restrict__ w,
                                 float* __restrict__ out32,
                                 __half* __restrict__ out16,
                                 int addx)
{
    const int row = blockIdx.x;
    const int tid = threadIdx.x;
    float v[3];
    float local = 0.f;
#pragma unroll
    for (int j = 0; j < 3; j++) {
        int c = tid + j * 256;
        float t = res[(size_t)row * Dm + c];
        if (addx) {
            t += xadd[(size_t)row * Dm + c];
            res[(size_t)row * Dm + c] = t;
        }
        v[j] = t;
        local += t * t;
    }
#pragma unroll
    for (int o = 16; o > 0; o >>= 1) local += __shfl_xor_sync(0xffffffffu, local, o);
    __shared__ float warpsum[8];
    __shared__ float sscale;
    if ((tid & 31) == 0) warpsum[tid >> 5] = local;
    __syncthreads();
    if (tid == 0) {
        float t = 0.f;
#pragma unroll
        for (int j = 0; j < 8; j++) t += warpsum[j];
        sscale = rsqrtf(t / (float)Dm + EPSf);
    }
    __syncthreads();
    float sc = sscale;
#pragma unroll
    for (int j = 0; j < 3; j++) {
        int c = tid + j * 256;
        float o = v[j] * sc * w[c];
        if (out32) out32[(size_t)row * Dm + c] = o;
        if (out16) out16[(size_t)row * Dm + c] = __float2half_rn(o);
    }
}

// ============================================================================
// Pure-FP16 tensor-core GEMM, fp32 accumulate, 2-stage cp.async, BK=32.
// 128 threads = 4 warps (2m x 2n); warp tile 64 x (BN/2).  (round-14 core)
// C[M,N] = A[M,K](fp16, lda) @ W[N,K]^T(fp16, row stride wstride).
// Optional split-K via gridDim.z (K = split length, C offset cspl per z).
// ============================================================================
template <int BN>
__global__ __launch_bounds__(128)
void hgemm16_tn(const __half* __restrict__ A, int lda,
                const __half* __restrict__ W, int wstride,
                float* __restrict__ C, int ldc, int K,
                size_t cspl)
{
    constexpr int BM = 128;
    constexpr int BK = 32;
    constexpr int LD = BK + 8;       // 40 halves
    constexpr int WM = 64;
    constexpr int WN = BN / 2;       // 64 or 32
    constexpr int AF = WM / 16;      // 4
    constexpr int BF = WN / 16;      // 4 or 2

    __shared__ __half As[2][BM][LD];
    __shared__ __half Ws[2][BN][LD];

    const int z = blockIdx.z;
    A += (size_t)z * K;
    W += (size_t)z * K;
    C += (size_t)z * cspl;

    const int t    = threadIdx.x;
    const int warp = t >> 5;
    const int wm   = (warp & 1) * WM;
    const int wn   = (warp >> 1) * WN;
    const int bm   = blockIdx.y * BM;
    const int bn   = blockIdx.x * BN;

    // loaders: vec8 unit u = t + i*128 -> row = u>>2, col = (u&3)*8
    const int lr = t >> 2;           // 0..31
    const int lc = (t & 3) * 8;

    auto issue = [&](int stage, int k0) {
#pragma unroll
        for (int i = 0; i < 4; i++) {       // A: 128 rows
            int r = lr + i * 32;
            cp16(&As[stage][r][lc], A + (size_t)(bm + r) * lda + k0 + lc);
        }
#pragma unroll
        for (int i = 0; i < BN / 32; i++) { // W: BN rows
            int r = lr + i * 32;
            cp16(&Ws[stage][r][lc], W + (size_t)(bn + r) * wstride + k0 + lc);
        }
        cp_commit();
    };

    wmma::fragment<wmma::accumulator, 16, 16, 16, float> acc[AF][BF];
#pragma unroll
    for (int i = 0; i < AF; i++)
#pragma unroll
        for (int j = 0; j < BF; j++)
            wmma::fill_fragment(acc[i][j], 0.f);

    const int nt = K / BK;

    issue(0, 0);
    cp_wait<0>();
    __syncthreads();

    for (int tt = 0; tt < nt; ++tt) {
        const int buf = tt & 1;
        const bool more = (tt + 1 < nt);
        if (more) issue(buf ^ 1, (tt + 1) * BK);

#pragma unroll
        for (int kk = 0; kk < BK; kk += 16) {
            wmma::fragment<wmma::matrix_a, 16, 16, 16, __half, wmma::row_major> af[AF];
            wmma::fragment<wmma::matrix_b, 16, 16, 16, __half, wmma::col_major> bf[BF];
#pragma unroll
            for (int i = 0; i < AF; i++)
                wmma::load_matrix_sync(af[i], &As[buf][wm + i * 16][kk], LD);
#pragma unroll
            for (int j = 0; j < BF; j++)
                wmma::load_matrix_sync(bf[j], &Ws[buf][wn + j * 16][kk], LD);
#pragma unroll
            for (int i = 0; i < AF; i++)
#pragma unroll
                for (int j = 0; j < BF; j++)
                    wmma::mma_sync(acc[i][j], af[i], bf[j], acc[i][j]);
        }

        if (more) cp_wait<0>();
        __syncthreads();
    }

#pragma unroll
    for (int i = 0; i < AF; i++)
#pragma unroll
        for (int j = 0; j < BF; j++)
            wmma::store_matrix_sync(&C[(size_t)(bm + wm + i * 16) * ldc + bn + wn + j * 16],
                                    acc[i][j], ldc, wmma::mem_row_major);
}

// ---------------- depthwise causal conv (K=4) + SiLU, fp32+fp16 out ----------------
__global__ void conv_silu_kernel(const float* __restrict__ xz,
                                 const float* __restrict__ w,
                                 const float* __restrict__ bias,
                                 float* __restrict__ xc,
                                 __half* __restrict__ xc16)
{
    int idx = blockIdx.x * blockDim.x + threadIdx.x;
    if (idx >= Mrows * DIm) return;
    int row = idx / DIm;
    int c   = idx - row * DIm;
    int l   = row & (Ll - 1);
    float s = bias[c];
#pragma unroll
    for (int k = 0; k < 4; k++) {
        int ll = l - 3 + k;
        if (ll >= 0) s += w[c * 4 + k] * xz[(size_t)(row - 3 + k) * (2 * DIm) + c];
    }
    float o = s / (1.f + expf(-s));
    xc[idx] = o;
    xc16[idx] = __float2half_rn(o);
}

// ============================================================================
// Chunked selective scan: 1 thread per (b, chunk, channel), 16 states in regs.
// ============================================================================
__device__ __forceinline__ float softplus_f(float x)
{
    return (x > 20.f) ? x : log1pf(__expf(x));
}

__global__ void scan_pass1(const float* __restrict__ xc,
                           const float* __restrict__ dtl,
                           const float* __restrict__ dbl,
                           const float* __restrict__ A_log,
                           const float* __restrict__ dtb_bias,
                           float* __restrict__ chk_end,
                           float* __restrict__ aprod)
{
    int d = blockIdx.x * blockDim.x + threadIdx.x;
    int c = blockIdx.y;
    int b = blockIdx.z;
    if (d >= DIm) return;

    float Ac[16], st[16];
#pragma unroll
    for (int n = 0; n < 16; n++) {
        Ac[n] = -expf(A_log[(size_t)d * 16 + n]);
        st[n] = 0.f;
    }
    const float db = dtb_bias[d];
    float sumdt = 0.f;

    const int l0 = c * CL;
    const float* xcb = xc  + ((size_t)b * Ll + l0) * DIm + d;
    const float* dtb = dtl + ((size_t)b * Ll + l0) * DIm + d;
    const float* blb = dbl + ((size_t)b * Ll + l0) * DBL_LD;

    for (int l = 0; l < CL; l++) {
        float u   = xcb[(size_t)l * DIm];
        float dtt = softplus_f(dtb[(size_t)l * DIm] + db);
        float du  = dtt * u;
        sumdt += dtt;
        const float4* B4 = (const float4*)(blb + (size_t)l * DBL_LD + 48);
#pragma unroll
        for (int j = 0; j < 4; j++) {
            float4 Bv = B4[j];
            st[4*j+0] = fmaf(__expf(dtt * Ac[4*j+0]), st[4*j+0], du * Bv.x);
            st[4*j+1] = fmaf(__expf(dtt * Ac[4*j+1]), st[4*j+1], du * Bv.y);
            st[4*j+2] = fmaf(__expf(dtt * Ac[4*j+2]), st[4*j+2], du * Bv.z);
            st[4*j+3] = fmaf(__expf(dtt * Ac[4*j+3]), st[4*j+3], du * Bv.w);
        }
    }
    size_t base = (((size_t)b * CH + c) * DIm + d) * 16;
#pragma unroll
    for (int n = 0; n < 16; n++) {
        chk_end[base + n] = st[n];
        aprod[base + n]   = __expf(sumdt * Ac[n]);
    }
}

__global__ void scan_pass2(const float* __restrict__ chk_end,
                           const float* __restrict__ aprod,
                           float* __restrict__ chk_pref)
{
    int idx = blockIdx.x * blockDim.x + threadIdx.x;
    if (idx >= Bb * DIm * Nst) return;
    int b = idx / (DIm * Nst);
    int r = idx - b * (DIm * Nst);
    float hv = 0.f;
#pragma unroll
    for (int c = 0; c < CH; c++) {
        size_t o = ((size_t)b * CH + c) * DIm * Nst + r;
        chk_pref[o] = hv;
        hv = fmaf(aprod[o], hv, chk_end[o]);
    }
}

__global__ void scan_pass3(const float* __restrict__ xc,
                           const float* __restrict__ dtl,
                           const float* __restrict__ dbl,
                           const float* __restrict__ A_log,
                           const float* __restrict__ dtb_bias,
                           const float* __restrict__ Dp,
                           const float* __restrict__ xz,
                           const float* __restrict__ chk_pref,
                           __half* __restrict__ y16)
{
    int d = blockIdx.x * blockDim.x + threadIdx.x;
    int c = blockIdx.y;
    int b = blockIdx.z;
    if (d >= DIm) return;

    float Ac[16], st[16];
#pragma unroll
    for (int n = 0; n < 16; n++)
        Ac[n] = -expf(A_log[(size_t)d * 16 + n]);
    {
        size_t base = (((size_t)b * CH + c) * DIm + d) * 16;
#pragma unroll
        for (int n = 0; n < 16; n++) st[n] = chk_pref[base + n];
    }
    const float db = dtb_bias[d];
    const float dp = Dp[d];

    const int l0 = c * CL;
    const float* xcb = xc  + ((size_t)b * Ll + l0) * DIm + d;
    const float* dtb = dtl + ((size_t)b * Ll + l0) * DIm + d;
    const float* zb  = xz  + ((size_t)b * Ll + l0) * (2 * DIm) + DIm + d;
    const float* blb = dbl + ((size_t)b * Ll + l0) * DBL_LD;
    __half*      yb  = y16 + ((size_t)b * Ll + l0) * DIm + d;

    for (int l = 0; l < CL; l++) {
        float u   = xcb[(size_t)l * DIm];
        float dtt = softplus_f(dtb[(size_t)l * DIm] + db);
        float du  = dtt * u;
        const float4* B4 = (const float4*)(blb + (size_t)l * DBL_LD + 48);
        const float4* C4 = (const float4*)(blb + (size_t)l * DBL_LD + 64);
        float yv = 0.f;
#pragma unroll
        for (int j = 0; j < 4; j++) {
            float4 Bv = B4[j];
            float4 Cv = C4[j];
            st[4*j+0] = fmaf(__expf(dtt * Ac[4*j+0]), st[4*j+0], du * Bv.x);
            st[4*j+1] = fmaf(__expf(dtt * Ac[4*j+1]), st[4*j+1], du * Bv.y);
            st[4*j+2] = fmaf(__expf(dtt * Ac[4*j+2]), st[4*j+2], du * Bv.z);
            st[4*j+3] = fmaf(__expf(dtt * Ac[4*j+3]), st[4*j+3], du * Bv.w);
            yv = fmaf(st[4*j+0], Cv.x, yv);
            yv = fmaf(st[4*j+1], Cv.y, yv);
            yv = fmaf(st[4*j+2], Cv.z, yv);
            yv = fmaf(st[4*j+3], Cv.w, yv);
        }
        float z = zb[(size_t)l * (2 * DIm)];
        yv = fmaf(u, dp, yv);
        yb[(size_t)l * DIm] = __float2half_rn(yv * (z / (1.f + __expf(-z))));
    }
}

// ---------------- host launcher ----------------
extern "C" void kernel_launch(void* const* d_in, const int* in_sizes, int n_in,
                              void* d_out, int out_size)
{
    const int*   ids       = (const int*)  d_in[0];
    const float* emb       = (const float*)d_in[1];
    const float* in_proj_w = (const float*)d_in[2];
    const float* conv_w    = (const float*)d_in[3];
    const float* conv_b    = (const float*)d_in[4];
    const float* x_proj_w  = (const float*)d_in[5];
    const float* dt_proj_w = (const float*)d_in[6];
    const float* dt_proj_b = (const float*)d_in[7];
    const float* A_log     = (const float*)d_in[8];
    const float* D_param   = (const float*)d_in[9];
    const float* out_proj_w= (const float*)d_in[10];
    const float* norm_w    = (const float*)d_in[11];
    const float* norm_f_w  = (const float*)d_in[12];
    float* out = (float*)d_out;

    float* s = nullptr;
    cudaGetSymbolAddress((void**)&s, g_scratch);
    __half* wh = nullptr;
    cudaGetSymbolAddress((void**)&wh, g_wh);
    __half* ah = nullptr;
    cudaGetSymbolAddress((void**)&ah, g_act);

    float* res = s + OFF_RES;
    float* x   = s + OFF_X;
    float* xz  = s + OFF_XZ;
    float* xc  = s + OFF_XC;
    float* dtl = s + OFF_DT;
    float* dbl = s + OFF_DBL;
    float* che = s + OFF_CHE;
    float* apr = s + OFF_APR;
    float* pre = s + OFF_PRE;
    float* spl = s + OFF_SPL;

    __half* w_in   = wh + HOFF_IN;
    __half* w_out  = wh + HOFF_OUT;
    __half* w_xw   = wh + HOFF_XW;
    __half* w_dw   = wh + HOFF_DW;
    __half* h16    = ah + AOFF_H16;
    __half* xc16   = ah + AOFF_XC16;
    __half* dbl16  = ah + AOFF_DBL16;
    __half* y16    = ah + AOFF_Y16;

    // 1) merged weight conversion / padding
    convert_weights_kernel<<<(int)((V_TOTAL + 255) / 256), 256>>>(
        in_proj_w, out_proj_w, x_proj_w, dt_proj_w, (uint4*)wh);

    // 2) embedding
    embed_kernel<<<(Mrows * Dm + 255) / 256, 256>>>(ids, emb, res);

    for (int i = 0; i < NLs; i++) {
        // 3) h16 = fp16(rms(res += x))
        rms_resid_kernel<<<Mrows, 256>>>(res, x, norm_w + (size_t)i * Dm,
                                         nullptr, h16, i > 0);

        // 4) xz = h16 @ in_proj^T   [2048, 3072], K=768   <- profiled launch
        {
            dim3 g(2 * DIm / 128, Mrows / 128, 1);
            hgemm16_tn<128><<<g, 128>>>(h16, Dm, w_in + (size_t)i * 2 * DIm * Dm, Dm,
                                        xz, 2 * DIm, Dm, 0);
        }

        // xc/xc16 = silu(causal depthwise conv(xi) + b)
        conv_silu_kernel<<<(Mrows * DIm + 255) / 256, 256>>>(
            xz, conv_w + (size_t)i * DIm * 4, conv_b + (size_t)i * DIm, xc, xc16);

        // dbl partials = xc16 @ xw_pad^T (split-K x SPK)  [2048, 128], K=1536
        {
            dim3 g(128 / 64, Mrows / 128, SPK);
            hgemm16_tn<64><<<g, 128>>>(xc16, DIm, w_xw + (size_t)i * 128 * DIm, DIm,
                                       spl, DBL_LD, DIm / SPK,
                                       (size_t)Mrows * DBL_LD);
        }

        // reduce partials -> dbl (fp32) + dbl16 (fp16)
        {
            int n4 = Mrows * DBL_LD / 4;
            reduce_spl_kernel<<<(n4 + 255) / 256, 256>>>(
                (const float4*)spl, (float4*)dbl, (uint2*)dbl16, n4);
        }

        // dt_lin = dbl16[:, :64] @ dw_pad^T   [2048, 1536], K=64
        {
            dim3 g(DIm / 128, Mrows / 128, 1);
            hgemm16_tn<128><<<g, 128>>>(dbl16, DBL_LD, w_dw + (size_t)i * DIm * 64, 64,
                                        dtl, DIm, 64, 0);
        }

        // chunked selective scan (1 thread / channel)
        {
            dim3 g1(DIm / 256, CH, Bb);
            scan_pass1<<<g1, 256>>>(xc, dtl, dbl, A_log + (size_t)i * DIm * Nst,
                                    dt_proj_b + (size_t)i * DIm, che, apr);
            scan_pass2<<<(Bb * DIm * Nst + 255) / 256, 256>>>(che, apr, pre);
            scan_pass3<<<g1, 256>>>(xc, dtl, dbl, A_log + (size_t)i * DIm * Nst,
                                    dt_proj_b + (size_t)i * DIm,
                                    D_param + (size_t)i * DIm, xz, pre, y16);
        }

        // x = y16 @ out_proj^T   [2048, 768], K=1536
        {
            dim3 g(Dm / 64, Mrows / 128, 1);
            hgemm16_tn<64><<<g, 128>>>(y16, DIm, w_out + (size_t)i * Dm * DIm, DIm,
                                       x, Dm, DIm, 0);
        }
    }

    // final: out = rms(res + x) * norm_f_w   (fp32)
    rms_resid_kernel<<<Mrows, 256>>>(res, x, norm_f_w, out, nullptr, 1);
}